// round 1
// baseline (speedup 1.0000x reference)
#include <cuda_runtime.h>
#include <math.h>

#define N_LANDMARKS 543
#define N_SEL       107
#define FIXED_FRAMES 30
#define OUT_ELEMS   (FIXED_FRAMES * N_SEL * 3)   // 9630
#define RED_BLOCKS  1184
#define RED_TPB     256

// MediaPipe Holistic selection: 40 lips | 21 left hand | 25 upper-body pose | 21 right hand
__constant__ int c_sel[N_SEL] = {
    61,185,40,39,37,0,267,269,270,409,291,146,91,181,84,17,314,405,321,375,
    78,191,80,81,82,13,312,311,310,415,95,88,178,87,14,317,402,318,324,308,
    468,469,470,471,472,473,474,475,476,477,478,479,480,481,482,483,484,485,
    486,487,488,
    489,490,491,492,493,494,495,496,497,498,499,500,501,502,503,504,505,506,
    507,508,509,510,511,512,513,
    522,523,524,525,526,527,528,529,530,531,532,533,534,535,536,537,538,539,
    540,541,542
};

// Per-block partials (overwritten fully every launch -> graph-replay safe)
__device__ double    g_s1[RED_BLOCKS];
__device__ double    g_s2[RED_BLOCKS];
__device__ long long g_cnt[RED_BLOCKS];

// ---------------------------------------------------------------------------
// Kernel 1: single-pass masked reduction of sum, sum of squares, count.
// fp32 per-thread accumulation (small partial -> negligible error), fp64 only
// at the warp/block fold so the weak FP64 pipe never sees the hot loop.
// ---------------------------------------------------------------------------
__global__ __launch_bounds__(RED_TPB)
void reduce_kernel(const float* __restrict__ x, int n)
{
    const int n4 = n >> 2;
    const float4* __restrict__ x4 = reinterpret_cast<const float4*>(x);

    float s1 = 0.f, s2 = 0.f;
    int   cnt = 0;

    const int stride = gridDim.x * blockDim.x;
    for (int i = blockIdx.x * blockDim.x + threadIdx.x; i < n4; i += stride) {
        float4 v = x4[i];
        if (v.x == v.x) { s1 += v.x; s2 = fmaf(v.x, v.x, s2); cnt++; }
        if (v.y == v.y) { s1 += v.y; s2 = fmaf(v.y, v.y, s2); cnt++; }
        if (v.z == v.z) { s1 += v.z; s2 = fmaf(v.z, v.z, s2); cnt++; }
        if (v.w == v.w) { s1 += v.w; s2 = fmaf(v.w, v.w, s2); cnt++; }
    }
    // tail (n % 4) — not hit for this problem's shape but kept for safety
    {
        int base = n4 << 2;
        int gtid = blockIdx.x * blockDim.x + threadIdx.x;
        if (gtid < (n - base)) {
            float v = x[base + gtid];
            if (v == v) { s1 += v; s2 = fmaf(v, v, s2); cnt++; }
        }
    }

    double    d1 = (double)s1;
    double    d2 = (double)s2;
    long long dc = (long long)cnt;

    #pragma unroll
    for (int o = 16; o > 0; o >>= 1) {
        d1 += __shfl_down_sync(0xffffffffu, d1, o);
        d2 += __shfl_down_sync(0xffffffffu, d2, o);
        dc += __shfl_down_sync(0xffffffffu, dc, o);
    }

    __shared__ double    sh1[8], sh2[8];
    __shared__ long long shc[8];
    const int lane = threadIdx.x & 31;
    const int warp = threadIdx.x >> 5;
    if (lane == 0) { sh1[warp] = d1; sh2[warp] = d2; shc[warp] = dc; }
    __syncthreads();

    if (warp == 0) {
        d1 = (lane < 8) ? sh1[lane] : 0.0;
        d2 = (lane < 8) ? sh2[lane] : 0.0;
        dc = (lane < 8) ? shc[lane] : 0ll;
        #pragma unroll
        for (int o = 4; o > 0; o >>= 1) {
            d1 += __shfl_down_sync(0xffffffffu, d1, o);
            d2 += __shfl_down_sync(0xffffffffu, d2, o);
            dc += __shfl_down_sync(0xffffffffu, dc, o);
        }
        if (lane == 0) {
            g_s1[blockIdx.x]  = d1;
            g_s2[blockIdx.x]  = d2;
            g_cnt[blockIdx.x] = dc;
        }
    }
}

// ---------------------------------------------------------------------------
// Kernel 2: fold partials (redundant per block, L2-resident), then each
// thread emits one output element: normalize + SEL gather + frame resample.
// ---------------------------------------------------------------------------
__global__ __launch_bounds__(256)
void gather_kernel(const float* __restrict__ x, float* __restrict__ out, int T)
{
    double    d1 = 0.0, d2 = 0.0;
    long long dc = 0;
    for (int i = threadIdx.x; i < RED_BLOCKS; i += blockDim.x) {
        d1 += g_s1[i];
        d2 += g_s2[i];
        dc += g_cnt[i];
    }
    #pragma unroll
    for (int o = 16; o > 0; o >>= 1) {
        d1 += __shfl_down_sync(0xffffffffu, d1, o);
        d2 += __shfl_down_sync(0xffffffffu, d2, o);
        dc += __shfl_down_sync(0xffffffffu, dc, o);
    }
    __shared__ double    sh1[8], sh2[8];
    __shared__ long long shc[8];
    __shared__ float     s_mean, s_istd;
    const int lane = threadIdx.x & 31;
    const int warp = threadIdx.x >> 5;
    if (lane == 0) { sh1[warp] = d1; sh2[warp] = d2; shc[warp] = dc; }
    __syncthreads();
    if (warp == 0) {
        d1 = (lane < 8) ? sh1[lane] : 0.0;
        d2 = (lane < 8) ? sh2[lane] : 0.0;
        dc = (lane < 8) ? shc[lane] : 0ll;
        #pragma unroll
        for (int o = 4; o > 0; o >>= 1) {
            d1 += __shfl_down_sync(0xffffffffu, d1, o);
            d2 += __shfl_down_sync(0xffffffffu, d2, o);
            dc += __shfl_down_sync(0xffffffffu, dc, o);
        }
        if (lane == 0) {
            double cnt  = (double)dc;
            double mean = d1 / cnt;
            // var of centered values, unbiased; second-pass m2 correction is
            // O(1e-12) and far below the 1e-3 tolerance.
            double var  = (d2 - d1 * d1 / cnt) / (cnt - 1.0);
            s_mean = (float)mean;
            s_istd = (float)(1.0 / sqrt(var));
        }
    }
    __syncthreads();

    const float mean = s_mean;
    const float istd = s_istd;

    const int o = blockIdx.x * blockDim.x + threadIdx.x;
    if (o >= OUT_ELEMS) return;

    const int f  = o / (N_SEL * 3);
    const int r  = o - f * (N_SEL * 3);
    const int l  = r / 3;
    const int cd = r - l * 3;
    const int lm = c_sel[l];

    if (T >= FIXED_FRAMES) {
        // nearest-exact: replicate JAX f32 arithmetic exactly:
        // scalar T/30 cast to f32 FIRST, then f32 multiply, then floor.
        const float scale = (float)((double)T / (double)FIXED_FRAMES);
        const float pos   = ((float)f + 0.5f) * scale;
        int src = (int)floorf(pos);
        if (src < 0)     src = 0;
        if (src > T - 1) src = T - 1;
        const float v = x[((long long)src * N_LANDMARKS + lm) * 3 + cd];
        out[o] = (v == v) ? (v - mean) * istd : 0.f;
    } else {
        // linear, align_corners=False (not hit for this shape; kept for safety)
        float pos = ((float)f + 0.5f) * ((float)T / (float)FIXED_FRAMES) - 0.5f;
        pos = fminf(fmaxf(pos, 0.f), (float)(T - 1));
        const int i0 = (int)floorf(pos);
        const int i1 = min(i0 + 1, T - 1);
        const float w = pos - (float)i0;
        const float v0 = x[((long long)i0 * N_LANDMARKS + lm) * 3 + cd];
        const float v1 = x[((long long)i1 * N_LANDMARKS + lm) * 3 + cd];
        const float y0 = (v0 == v0) ? (v0 - mean) * istd : 0.f;
        const float y1 = (v1 == v1) ? (v1 - mean) * istd : 0.f;
        out[o] = (1.f - w) * y0 + w * y1;
    }
}

// ---------------------------------------------------------------------------
extern "C" void kernel_launch(void* const* d_in, const int* in_sizes, int n_in,
                              void* d_out, int out_size)
{
    const float* x = (const float*)d_in[0];
    const int n = in_sizes[0];
    const int T = n / (N_LANDMARKS * 3);

    reduce_kernel<<<RED_BLOCKS, RED_TPB>>>(x, n);

    const int gblocks = (OUT_ELEMS + 255) / 256;
    gather_kernel<<<gblocks, 256>>>(x, (float*)d_out, T);
}